// round 2
// baseline (speedup 1.0000x reference)
#include <cuda_runtime.h>
#include <math.h>

#define SEQ    4096
#define NH     16
#define HD     80
#define HIDDEN 1280
#define QKVN   3840
#define INV_SCALE 0.11180339887498948f   // 1/sqrt(80)

// -------- scratch (no allocation allowed -> __device__ globals) --------
__device__ float g_qkv [SEQ * QKVN];    // 62.9 MB : [seq][3*hidden]
__device__ float g_attn[SEQ * HIDDEN];  // 21.0 MB : attention output

// =====================================================================
// SGEMM: C[M,N] = A[M,K] @ B[K,N] + bias[N]
// 128x128 tile, BK=8, 256 threads, 8x8 micro-tile.
// Requires M%128==0, N%128==0, K%8==0, K%4==0 (all true here).
// =====================================================================
__global__ void __launch_bounds__(256)
sgemm_bias(const float* __restrict__ A, const float* __restrict__ B,
           const float* __restrict__ bias, float* __restrict__ C,
           int M, int N, int K)
{
    const int BM = 128, BN = 128, BK = 8, TM = 8, TN = 8;
    __shared__ float As[BK][BM];
    __shared__ float Bs[BK][BN];

    int tid = threadIdx.x;
    int tx = tid % 16;          // col group
    int ty = tid / 16;          // row group
    int bx = blockIdx.x, by = blockIdx.y;

    const float* Ab = A + (size_t)by * BM * K;
    const float* Bb = B + (size_t)bx * BN;

    // load maps
    int arow = tid >> 1;              // 0..127
    int acol = (tid & 1) * 4;         // 0 or 4
    int brow = tid >> 5;              // 0..7
    int bcol = (tid & 31) * 4;        // 0..124

    float acc[TM][TN];
    #pragma unroll
    for (int i = 0; i < TM; i++)
        #pragma unroll
        for (int j = 0; j < TN; j++) acc[i][j] = 0.f;

    for (int k0 = 0; k0 < K; k0 += BK) {
        float4 a4 = *(const float4*)&Ab[(size_t)arow * K + k0 + acol];
        As[acol + 0][arow] = a4.x;
        As[acol + 1][arow] = a4.y;
        As[acol + 2][arow] = a4.z;
        As[acol + 3][arow] = a4.w;
        float4 b4 = *(const float4*)&Bb[(size_t)(k0 + brow) * N + bcol];
        *(float4*)&Bs[brow][bcol] = b4;
        __syncthreads();

        #pragma unroll
        for (int k = 0; k < BK; k++) {
            float ra[TM], rb[TN];
            *(float4*)&ra[0] = *(const float4*)&As[k][ty * TM];
            *(float4*)&ra[4] = *(const float4*)&As[k][ty * TM + 4];
            *(float4*)&rb[0] = *(const float4*)&Bs[k][tx * TN];
            *(float4*)&rb[4] = *(const float4*)&Bs[k][tx * TN + 4];
            #pragma unroll
            for (int i = 0; i < TM; i++)
                #pragma unroll
                for (int j = 0; j < TN; j++)
                    acc[i][j] = fmaf(ra[i], rb[j], acc[i][j]);
        }
        __syncthreads();
    }

    #pragma unroll
    for (int i = 0; i < TM; i++) {
        size_t row = (size_t)by * BM + ty * TM + i;
        #pragma unroll
        for (int j = 0; j < TN; j += 4) {
            int col = bx * BN + tx * TN + j;
            float4 c4;
            c4.x = acc[i][j + 0] + bias[col + 0];
            c4.y = acc[i][j + 1] + bias[col + 1];
            c4.z = acc[i][j + 2] + bias[col + 2];
            c4.w = acc[i][j + 3] + bias[col + 3];
            *(float4*)&C[row * N + col] = c4;
        }
    }
}

// =====================================================================
// RoPE in-place on Q and K halves of g_qkv.
// out[:40]  = t1*c1 - t2*s1 ;  out[40:] = t2*c2 + t1*s2
// =====================================================================
__global__ void rope_kernel(const float* __restrict__ cosE,
                            const float* __restrict__ sinE)
{
    int idx = blockIdx.x * blockDim.x + threadIdx.x;
    const int TOT = 2 * SEQ * NH * (HD / 2);
    if (idx >= TOT) return;
    int d    = idx % 40;
    int h    = (idx / 40) % NH;
    int s    = (idx / (40 * NH)) % SEQ;
    int part = idx / (40 * NH * SEQ);      // 0 = Q, 1 = K

    float* p = g_qkv + (size_t)s * QKVN + part * HIDDEN + h * HD;
    float t1 = p[d], t2 = p[d + 40];
    float c1 = cosE[s * HD + d],      s1 = sinE[s * HD + d];
    float c2 = cosE[s * HD + d + 40], s2 = sinE[s * HD + d + 40];
    p[d]      = t1 * c1 - t2 * s1;
    p[d + 40] = t2 * c2 + t1 * s2;
}

// =====================================================================
// Flash attention, fp32, online softmax.
// grid = (SEQ/64, NH), block = 256.
// Thread layout: tr = tid/16 (4 query rows), tc = tid%16 (4 key cols for S,
// 5 head-dims for O). Row-group = 16 contiguous lanes (half warp).
// =====================================================================
#define FA_DP 68                       // padded 64 (row len of Qt/Kt/Ss)
#define FA_VP 84                       // padded 80 (row len of Vs)
#define FA_SMEM_FLOATS (HD*FA_DP + HD*FA_DP + 64*FA_VP + 64*FA_DP)
#define FA_SMEM_BYTES  (FA_SMEM_FLOATS * 4)

__global__ void __launch_bounds__(256)
flash_attn_kernel()
{
    extern __shared__ float sm[];
    float* Qt = sm;                    // [HD][68]  (dim-major, transposed)
    float* Kt = Qt + HD * FA_DP;       // [HD][68]
    float* Vs = Kt + HD * FA_DP;       // [64][84]  (key-major)
    float* Ss = Vs + 64 * FA_VP;       // [64][68]  (P tile)

    int tid = threadIdx.x;
    int tc  = tid % 16;
    int tr  = tid / 16;
    int h   = blockIdx.y;
    int q0  = blockIdx.x * 64;

    // ---- load Q tile (pre-scaled) transposed ----
    const float* qg = g_qkv + (size_t)q0 * QKVN + h * HD;
    for (int i = tid; i < 64 * HD; i += 256) {
        int r = i / HD, d = i % HD;
        Qt[d * FA_DP + r] = qg[(size_t)r * QKVN + d] * INV_SCALE;
    }

    float o[4][5];
    float m[4], l[4];
    #pragma unroll
    for (int i = 0; i < 4; i++) {
        m[i] = -3.0e38f; l[i] = 0.f;
        #pragma unroll
        for (int j = 0; j < 5; j++) o[i][j] = 0.f;
    }
    __syncthreads();

    for (int kt = 0; kt < SEQ / 64; kt++) {
        int k0 = kt * 64;
        const float* kg = g_qkv + (size_t)k0 * QKVN + HIDDEN     + h * HD;
        const float* vg = g_qkv + (size_t)k0 * QKVN + 2 * HIDDEN + h * HD;
        for (int i = tid; i < 64 * HD; i += 256) {
            int c = i / HD, d = i % HD;
            Kt[d * FA_DP + c] = kg[(size_t)c * QKVN + d];
            Vs[c * FA_VP + d] = vg[(size_t)c * QKVN + d];
        }
        __syncthreads();

        // ---- S = Q K^T (4x4 per thread) ----
        float acc[4][4];
        #pragma unroll
        for (int i = 0; i < 4; i++)
            #pragma unroll
            for (int j = 0; j < 4; j++) acc[i][j] = 0.f;

        #pragma unroll 4
        for (int k = 0; k < HD; k++) {
            float4 q4 = *(const float4*)&Qt[k * FA_DP + 4 * tr];
            float4 k4 = *(const float4*)&Kt[k * FA_DP + 4 * tc];
            float qa[4] = {q4.x, q4.y, q4.z, q4.w};
            float kb[4] = {k4.x, k4.y, k4.z, k4.w};
            #pragma unroll
            for (int i = 0; i < 4; i++)
                #pragma unroll
                for (int j = 0; j < 4; j++)
                    acc[i][j] = fmaf(qa[i], kb[j], acc[i][j]);
        }

        // ---- online softmax (row group = 16 lanes in same half-warp) ----
        #pragma unroll
        for (int i = 0; i < 4; i++) {
            float rmax = fmaxf(fmaxf(acc[i][0], acc[i][1]),
                               fmaxf(acc[i][2], acc[i][3]));
            #pragma unroll
            for (int w = 1; w < 16; w <<= 1)
                rmax = fmaxf(rmax, __shfl_xor_sync(0xffffffffu, rmax, w));
            float mn    = fmaxf(m[i], rmax);
            float alpha = __expf(m[i] - mn);
            float rs = 0.f;
            #pragma unroll
            for (int j = 0; j < 4; j++) {
                float p = __expf(acc[i][j] - mn);
                Ss[(4 * tr + i) * FA_DP + 4 * tc + j] = p;
                rs += p;
            }
            #pragma unroll
            for (int w = 1; w < 16; w <<= 1)
                rs += __shfl_xor_sync(0xffffffffu, rs, w);
            l[i] = l[i] * alpha + rs;
            m[i] = mn;
            #pragma unroll
            for (int j = 0; j < 5; j++) o[i][j] *= alpha;
        }
        __syncwarp();   // Ss rows only touched by lanes of same warp

        // ---- O += P V ----
        #pragma unroll 2
        for (int c = 0; c < 64; c++) {
            float vj[5];
            #pragma unroll
            for (int j = 0; j < 5; j++) vj[j] = Vs[c * FA_VP + 5 * tc + j];
            #pragma unroll
            for (int i = 0; i < 4; i++) {
                float p = Ss[(4 * tr + i) * FA_DP + c];
                #pragma unroll
                for (int j = 0; j < 5; j++)
                    o[i][j] = fmaf(p, vj[j], o[i][j]);
            }
        }
        __syncthreads();   // before next tile overwrites Kt/Vs
    }

    // ---- epilogue ----
    #pragma unroll
    for (int i = 0; i < 4; i++) {
        float inv_l = 1.0f / l[i];
        size_t row = (size_t)(q0 + 4 * tr + i);
        #pragma unroll
        for (int j = 0; j < 5; j++)
            g_attn[row * HIDDEN + h * HD + 5 * tc + j] = o[i][j] * inv_l;
    }
}

// =====================================================================
extern "C" void kernel_launch(void* const* d_in, const int* in_sizes, int n_in,
                              void* d_out, int out_size)
{
    const float* x      = (const float*)d_in[0];
    const float* cosE   = (const float*)d_in[1];
    const float* sinE   = (const float*)d_in[2];
    const float* w_qkv  = (const float*)d_in[3];
    const float* b_qkv  = (const float*)d_in[4];
    const float* w_proj = (const float*)d_in[5];
    const float* b_proj = (const float*)d_in[6];
    float*       out    = (float*)d_out;

    float *qkv, *attn;
    cudaGetSymbolAddress((void**)&qkv,  g_qkv);
    cudaGetSymbolAddress((void**)&attn, g_attn);

    cudaFuncSetAttribute(flash_attn_kernel,
                         cudaFuncAttributeMaxDynamicSharedMemorySize,
                         FA_SMEM_BYTES);

    // 1) QKV GEMM : [4096,1280] @ [1280,3840] + bias
    sgemm_bias<<<dim3(QKVN / 128, SEQ / 128), 256>>>(
        x, w_qkv, b_qkv, qkv, SEQ, QKVN, HIDDEN);

    // 2) RoPE on Q and K
    {
        int tot = 2 * SEQ * NH * (HD / 2);
        rope_kernel<<<(tot + 255) / 256, 256>>>(cosE, sinE);
    }

    // 3) flash attention
    flash_attn_kernel<<<dim3(SEQ / 64, NH), 256, FA_SMEM_BYTES>>>();

    // 4) output projection : [4096,1280] @ [1280,1280] + bias
    sgemm_bias<<<dim3(HIDDEN / 128, SEQ / 128), 256>>>(
        attn, w_proj, b_proj, out, SEQ, HIDDEN, HIDDEN);
}

// round 3
// speedup vs baseline: 1.0907x; 1.0907x over previous
#include <cuda_runtime.h>
#include <math.h>

#define SEQ    4096
#define NH     16
#define HD     80
#define HIDDEN 1280
#define QKVN   3840
#define INV_SCALE 0.11180339887498948f   // 1/sqrt(80)

// -------- scratch (no allocation allowed -> __device__ globals) --------
__device__ float g_qkv [SEQ * QKVN];    // 62.9 MB : [seq][3*hidden]
__device__ float g_attn[SEQ * HIDDEN];  // 21.0 MB : attention output

// =====================================================================
// SGEMM: C[M,N] = A[M,K] @ B[K,N] + bias[N]
// 128x128 tile, BK=8, 256 threads, 8x8 micro-tile.
// =====================================================================
__global__ void __launch_bounds__(256)
sgemm_bias(const float* __restrict__ A, const float* __restrict__ B,
           const float* __restrict__ bias, float* __restrict__ C,
           int M, int N, int K)
{
    const int BM = 128, BN = 128, BK = 8, TM = 8, TN = 8;
    __shared__ float As[BK][BM];
    __shared__ float Bs[BK][BN];

    int tid = threadIdx.x;
    int tx = tid % 16;
    int ty = tid / 16;
    int bx = blockIdx.x, by = blockIdx.y;

    const float* Ab = A + (size_t)by * BM * K;
    const float* Bb = B + (size_t)bx * BN;

    int arow = tid >> 1;
    int acol = (tid & 1) * 4;
    int brow = tid >> 5;
    int bcol = (tid & 31) * 4;

    float acc[TM][TN];
    #pragma unroll
    for (int i = 0; i < TM; i++)
        #pragma unroll
        for (int j = 0; j < TN; j++) acc[i][j] = 0.f;

    for (int k0 = 0; k0 < K; k0 += BK) {
        float4 a4 = *(const float4*)&Ab[(size_t)arow * K + k0 + acol];
        As[acol + 0][arow] = a4.x;
        As[acol + 1][arow] = a4.y;
        As[acol + 2][arow] = a4.z;
        As[acol + 3][arow] = a4.w;
        float4 b4 = *(const float4*)&Bb[(size_t)(k0 + brow) * N + bcol];
        *(float4*)&Bs[brow][bcol] = b4;
        __syncthreads();

        #pragma unroll
        for (int k = 0; k < BK; k++) {
            float ra[TM], rb[TN];
            *(float4*)&ra[0] = *(const float4*)&As[k][ty * TM];
            *(float4*)&ra[4] = *(const float4*)&As[k][ty * TM + 4];
            *(float4*)&rb[0] = *(const float4*)&Bs[k][tx * TN];
            *(float4*)&rb[4] = *(const float4*)&Bs[k][tx * TN + 4];
            #pragma unroll
            for (int i = 0; i < TM; i++)
                #pragma unroll
                for (int j = 0; j < TN; j++)
                    acc[i][j] = fmaf(ra[i], rb[j], acc[i][j]);
        }
        __syncthreads();
    }

    #pragma unroll
    for (int i = 0; i < TM; i++) {
        size_t row = (size_t)by * BM + ty * TM + i;
        #pragma unroll
        for (int j = 0; j < TN; j += 4) {
            int col = bx * BN + tx * TN + j;
            float4 c4;
            c4.x = acc[i][j + 0] + bias[col + 0];
            c4.y = acc[i][j + 1] + bias[col + 1];
            c4.z = acc[i][j + 2] + bias[col + 2];
            c4.w = acc[i][j + 3] + bias[col + 3];
            *(float4*)&C[row * N + col] = c4;
        }
    }
}

// =====================================================================
// RoPE in-place on Q and K halves of g_qkv.
// =====================================================================
__global__ void rope_kernel(const float* __restrict__ cosE,
                            const float* __restrict__ sinE)
{
    int idx = blockIdx.x * blockDim.x + threadIdx.x;
    const int TOT = 2 * SEQ * NH * (HD / 2);
    if (idx >= TOT) return;
    int d    = idx % 40;
    int h    = (idx / 40) % NH;
    int s    = (idx / (40 * NH)) % SEQ;
    int part = idx / (40 * NH * SEQ);

    float* p = g_qkv + (size_t)s * QKVN + part * HIDDEN + h * HD;
    float t1 = p[d], t2 = p[d + 40];
    float c1 = cosE[s * HD + d],      s1 = sinE[s * HD + d];
    float c2 = cosE[s * HD + d + 40], s2 = sinE[s * HD + d + 40];
    p[d]      = t1 * c1 - t2 * s1;
    p[d + 40] = t2 * c2 + t1 * s2;
}

// =====================================================================
// Flash attention v2: BM=128 x BN=128 tile, 8x8 micro-tile, 256 threads.
// Qt/Kt dim-major [HD][128+pad]; Vs key-major [128][84];
// Ss (P tile) row-major [128][128].
// Row group = 16 contiguous lanes (half warp) -> shfl reductions + syncwarp.
// =====================================================================
#define FBM 128
#define FBN 128
#define FRP 132                       // pad for Qt/Kt rows (128 -> 132)
#define FVP 84                        // pad for Vs rows (80 -> 84)
#define FA2_SMEM_FLOATS (HD*FRP + HD*FRP + FBN*FVP + FBM*FBN)
#define FA2_SMEM_BYTES  (FA2_SMEM_FLOATS * 4)

__global__ void __launch_bounds__(256, 1)
flash_attn_kernel()
{
    extern __shared__ float sm[];
    float* Qt = sm;                    // [HD][FRP]
    float* Kt = Qt + HD * FRP;         // [HD][FRP]
    float* Vs = Kt + HD * FRP;         // [FBN][FVP]
    float* Ss = Vs + FBN * FVP;        // [FBM][FBN]

    int tid = threadIdx.x;
    int tc  = tid % 16;                // col group (8 cols / 5 dims)
    int tr  = tid / 16;                // row group (8 rows)
    int h   = blockIdx.y;
    int q0  = blockIdx.x * FBM;

    // ---- load Q tile transposed, pre-scaled. c-major lane map:
    // consecutive lanes -> consecutive q rows -> conflict-free STS.
    const float* qg = g_qkv + (size_t)q0 * QKVN + h * HD;
    for (int idx = tid; idx < FBM * (HD / 4); idx += 256) {
        int r  = idx % FBM;
        int dq = idx / FBM;            // 0..19
        float4 v = *(const float4*)&qg[(size_t)r * QKVN + 4 * dq];
        Qt[(4 * dq + 0) * FRP + r] = v.x * INV_SCALE;
        Qt[(4 * dq + 1) * FRP + r] = v.y * INV_SCALE;
        Qt[(4 * dq + 2) * FRP + r] = v.z * INV_SCALE;
        Qt[(4 * dq + 3) * FRP + r] = v.w * INV_SCALE;
    }

    float o[8][5];
    float m[8], l[8];
    #pragma unroll
    for (int i = 0; i < 8; i++) {
        m[i] = -3.0e38f; l[i] = 0.f;
        #pragma unroll
        for (int j = 0; j < 5; j++) o[i][j] = 0.f;
    }
    __syncthreads();

    for (int kt = 0; kt < SEQ / FBN; kt++) {
        int k0 = kt * FBN;
        const float* kg = g_qkv + (size_t)k0 * QKVN + HIDDEN     + h * HD;
        const float* vg = g_qkv + (size_t)k0 * QKVN + 2 * HIDDEN + h * HD;

        // Kt transposed: c-major map (conflict-free STS)
        for (int idx = tid; idx < FBN * (HD / 4); idx += 256) {
            int c  = idx % FBN;
            int dq = idx / FBN;
            float4 v = *(const float4*)&kg[(size_t)c * QKVN + 4 * dq];
            Kt[(4 * dq + 0) * FRP + c] = v.x;
            Kt[(4 * dq + 1) * FRP + c] = v.y;
            Kt[(4 * dq + 2) * FRP + c] = v.z;
            Kt[(4 * dq + 3) * FRP + c] = v.w;
        }
        // Vs row-major: d-major map (coalesced gmem, vector STS)
        for (int idx = tid; idx < FBN * (HD / 4); idx += 256) {
            int c  = idx / (HD / 4);
            int dq = idx % (HD / 4);
            *(float4*)&Vs[c * FVP + 4 * dq] =
                *(const float4*)&vg[(size_t)c * QKVN + 4 * dq];
        }
        __syncthreads();

        // ---- S = Q K^T (8x8 per thread) ----
        float acc[8][8];
        #pragma unroll
        for (int i = 0; i < 8; i++)
            #pragma unroll
            for (int j = 0; j < 8; j++) acc[i][j] = 0.f;

        #pragma unroll 2
        for (int k = 0; k < HD; k++) {
            float qa[8], kb[8];
            *(float4*)&qa[0] = *(const float4*)&Qt[k * FRP + 8 * tr];
            *(float4*)&qa[4] = *(const float4*)&Qt[k * FRP + 8 * tr + 4];
            *(float4*)&kb[0] = *(const float4*)&Kt[k * FRP + 8 * tc];
            *(float4*)&kb[4] = *(const float4*)&Kt[k * FRP + 8 * tc + 4];
            #pragma unroll
            for (int i = 0; i < 8; i++)
                #pragma unroll
                for (int j = 0; j < 8; j++)
                    acc[i][j] = fmaf(qa[i], kb[j], acc[i][j]);
        }

        // ---- online softmax per row (16-lane row group) ----
        #pragma unroll
        for (int i = 0; i < 8; i++) {
            float rmax = acc[i][0];
            #pragma unroll
            for (int j = 1; j < 8; j++) rmax = fmaxf(rmax, acc[i][j]);
            #pragma unroll
            for (int w = 1; w < 16; w <<= 1)
                rmax = fmaxf(rmax, __shfl_xor_sync(0xffffffffu, rmax, w));
            float mn    = fmaxf(m[i], rmax);
            float alpha = __expf(m[i] - mn);
            float p[8];
            float rs = 0.f;
            #pragma unroll
            for (int j = 0; j < 8; j++) {
                p[j] = __expf(acc[i][j] - mn);
                rs += p[j];
            }
            *(float4*)&Ss[(8 * tr + i) * FBN + 8 * tc]     = *(float4*)&p[0];
            *(float4*)&Ss[(8 * tr + i) * FBN + 8 * tc + 4] = *(float4*)&p[4];
            #pragma unroll
            for (int w = 1; w < 16; w <<= 1)
                rs += __shfl_xor_sync(0xffffffffu, rs, w);
            l[i] = l[i] * alpha + rs;
            m[i] = mn;
            #pragma unroll
            for (int j = 0; j < 5; j++) o[i][j] *= alpha;
        }
        __syncwarp();   // Ss rows written/read by same half-warp only

        // ---- O += P V ----
        #pragma unroll 2
        for (int c = 0; c < FBN; c++) {
            float vj[5];
            #pragma unroll
            for (int j = 0; j < 5; j++) vj[j] = Vs[c * FVP + 5 * tc + j];
            #pragma unroll
            for (int i = 0; i < 8; i++) {
                float p = Ss[(8 * tr + i) * FBN + c];   // broadcast load
                #pragma unroll
                for (int j = 0; j < 5; j++)
                    o[i][j] = fmaf(p, vj[j], o[i][j]);
            }
        }
        __syncthreads();   // before next tile overwrites Kt/Vs
    }

    // ---- epilogue ----
    #pragma unroll
    for (int i = 0; i < 8; i++) {
        float inv_l = 1.0f / l[i];
        size_t row = (size_t)(q0 + 8 * tr + i);
        #pragma unroll
        for (int j = 0; j < 5; j++)
            g_attn[row * HIDDEN + h * HD + 5 * tc + j] = o[i][j] * inv_l;
    }
}

// =====================================================================
extern "C" void kernel_launch(void* const* d_in, const int* in_sizes, int n_in,
                              void* d_out, int out_size)
{
    const float* x      = (const float*)d_in[0];
    const float* cosE   = (const float*)d_in[1];
    const float* sinE   = (const float*)d_in[2];
    const float* w_qkv  = (const float*)d_in[3];
    const float* b_qkv  = (const float*)d_in[4];
    const float* w_proj = (const float*)d_in[5];
    const float* b_proj = (const float*)d_in[6];
    float*       out    = (float*)d_out;

    float *qkv, *attn;
    cudaGetSymbolAddress((void**)&qkv,  g_qkv);
    cudaGetSymbolAddress((void**)&attn, g_attn);

    cudaFuncSetAttribute(flash_attn_kernel,
                         cudaFuncAttributeMaxDynamicSharedMemorySize,
                         FA2_SMEM_BYTES);

    // 1) QKV GEMM : [4096,1280] @ [1280,3840] + bias
    sgemm_bias<<<dim3(QKVN / 128, SEQ / 128), 256>>>(
        x, w_qkv, b_qkv, qkv, SEQ, QKVN, HIDDEN);

    // 2) RoPE on Q and K
    {
        int tot = 2 * SEQ * NH * (HD / 2);
        rope_kernel<<<(tot + 255) / 256, 256>>>(cosE, sinE);
    }

    // 3) flash attention (BM=BN=128)
    flash_attn_kernel<<<dim3(SEQ / FBM, NH), 256, FA2_SMEM_BYTES>>>();

    // 4) output projection : [4096,1280] @ [1280,1280] + bias
    sgemm_bias<<<dim3(HIDDEN / 128, SEQ / 128), 256>>>(
        attn, w_proj, b_proj, out, SEQ, HIDDEN, HIDDEN);
}